// round 11
// baseline (speedup 1.0000x reference)
#include <cuda_runtime.h>
#include <cuda_bf16.h>
#include <math.h>
#include <stdint.h>

using bf16 = __nv_bfloat16;

constexpr int Bc  = 4;
constexpr int Sc  = 2048;
constexpr int Dc  = 1024;
constexpr int Hc  = 16;
constexpr int DKc = 64;
constexpr int Mrows = Bc * Sc;     // 8192
constexpr int Ec    = Hc * DKc;    // 1024

// Device-global scratch (allocation-free per harness rules)
__device__ bf16 g_Xh[(size_t)Mrows * Dc];
__device__ bf16 g_Xl[(size_t)Mrows * Dc];
__device__ bf16 g_Wh[(size_t)4 * Dc * Ec];
__device__ bf16 g_Wl[(size_t)4 * Dc * Ec];
__device__ bf16 g_Qh[(size_t)Mrows * Ec];
__device__ bf16 g_Ql[(size_t)Mrows * Ec];
__device__ bf16 g_Kh[(size_t)Mrows * Ec];
__device__ bf16 g_Kl[(size_t)Mrows * Ec];
__device__ bf16 g_Vh[(size_t)Mrows * Ec];
__device__ bf16 g_Vl[(size_t)Mrows * Ec];
__device__ bf16 g_Vth[(size_t)Bc * Hc * DKc * Sc];  // [bh][dk][s]
__device__ bf16 g_Vtl[(size_t)Bc * Hc * DKc * Sc];
__device__ bf16 g_Ch[(size_t)Mrows * Ec];
__device__ bf16 g_Cl[(size_t)Mrows * Ec];

__device__ __forceinline__ uint32_t pack2(bf16 a, bf16 b) {
    __nv_bfloat162 t; t.x = a; t.y = b;
    return *reinterpret_cast<uint32_t*>(&t);
}
__device__ __forceinline__ void split2(float x, float y, uint32_t& hi, uint32_t& lo) {
    bf16 hx = __float2bfloat16(x), hy = __float2bfloat16(y);
    bf16 lx = __float2bfloat16(x - __bfloat162float(hx));
    bf16 ly = __float2bfloat16(y - __bfloat162float(hy));
    hi = pack2(hx, hy); lo = pack2(lx, ly);
}
__device__ __forceinline__ void mma_bf16(float* c,
        uint32_t a0, uint32_t a1, uint32_t a2, uint32_t a3,
        uint32_t b0, uint32_t b1) {
    asm volatile(
        "mma.sync.aligned.m16n8k16.row.col.f32.bf16.bf16.f32 "
        "{%0,%1,%2,%3}, {%4,%5,%6,%7}, {%8,%9}, {%0,%1,%2,%3};\n"
        : "+f"(c[0]), "+f"(c[1]), "+f"(c[2]), "+f"(c[3])
        : "r"(a0), "r"(a1), "r"(a2), "r"(a3), "r"(b0), "r"(b1));
}

// fp32 -> bf16 hi/lo split. which==0 -> X, 1..4 -> W slot.
__global__ __launch_bounds__(256) void split_kernel(const float* __restrict__ x, int which) {
    bf16 *hi, *lo;
    if (which == 0) { hi = g_Xh; lo = g_Xl; }
    else { size_t off = (size_t)(which - 1) * Dc * Ec; hi = g_Wh + off; lo = g_Wl + off; }
    size_t i = ((size_t)blockIdx.x * 256 + threadIdx.x) * 4;
    float4 v = *reinterpret_cast<const float4*>(x + i);
    bf16 h0 = __float2bfloat16(v.x), h1 = __float2bfloat16(v.y);
    bf16 h2 = __float2bfloat16(v.z), h3 = __float2bfloat16(v.w);
    bf16 l0 = __float2bfloat16(v.x - __bfloat162float(h0));
    bf16 l1 = __float2bfloat16(v.y - __bfloat162float(h1));
    bf16 l2 = __float2bfloat16(v.z - __bfloat162float(h2));
    bf16 l3 = __float2bfloat16(v.w - __bfloat162float(h3));
    uint2 H, L;
    H.x = pack2(h0, h1); H.y = pack2(h2, h3);
    L.x = pack2(l0, l1); L.y = pack2(l2, l3);
    *reinterpret_cast<uint2*>(hi + i) = H;
    *reinterpret_cast<uint2*>(lo + i) = L;
}

// V transpose: [b][s][h*64+dk] -> [bh][dk][s]
__global__ __launch_bounds__(256) void vtrans_kernel() {
    __shared__ bf16 th[32][33], tl[32][33];
    const int s0 = blockIdx.x * 32, d0 = blockIdx.y * 32, bh = blockIdx.z;
    const int b = bh >> 4, h = bh & 15;
    #pragma unroll
    for (int j = 0; j < 4; ++j) {
        int s = s0 + threadIdx.y + j * 8;
        size_t src = (size_t)(b * Sc + s) * Ec + h * DKc + d0 + threadIdx.x;
        th[threadIdx.y + j * 8][threadIdx.x] = g_Vh[src];
        tl[threadIdx.y + j * 8][threadIdx.x] = g_Vl[src];
    }
    __syncthreads();
    #pragma unroll
    for (int j = 0; j < 4; ++j) {
        int d = d0 + threadIdx.y + j * 8;
        size_t dst = (size_t)bh * DKc * Sc + (size_t)d * Sc + s0 + threadIdx.x;
        g_Vth[dst] = th[threadIdx.x][threadIdx.y + j * 8];
        g_Vtl[dst] = tl[threadIdx.x][threadIdx.y + j * 8];
    }
}

// ---------------------------------------------------------------------------
// bf16x3 GEMM: C[m][n] = sum_k A[m][k]*B[n][k]; N=K=1024.
// BM=128, BN=128, BK=32, 256 threads, warps 2(m)x4(n). Smem stride 40 bf16.
// ---------------------------------------------------------------------------
template<bool BF16OUT>
__device__ __forceinline__ void gemm_body(
    const bf16* __restrict__ Ah, const bf16* __restrict__ Al,
    const bf16* __restrict__ Bh, const bf16* __restrict__ Bl,
    float* __restrict__ Cf, bf16* __restrict__ Ch, bf16* __restrict__ Cl)
{
    constexpr int KD = 1024, ND = 1024, ST = 40;
    __shared__ bf16 sAh[128 * ST], sAl[128 * ST], sBh[128 * ST], sBl[128 * ST];

    const int tid = threadIdx.x;
    const int wid = tid >> 5, lid = tid & 31;
    const int wm = wid >> 2, wn = wid & 3;
    const int g = lid >> 2, qd = lid & 3;
    const int m0 = blockIdx.y * 128, n0 = blockIdx.x * 128;

    float acc[4][4][4];
    #pragma unroll
    for (int a = 0; a < 4; ++a)
        #pragma unroll
        for (int b = 0; b < 4; ++b)
            #pragma unroll
            for (int c = 0; c < 4; ++c) acc[a][b][c] = 0.f;

    uint4 pAh[2], pAl[2], pBh[2], pBl[2];
    const int lr = tid >> 2, lc = (tid & 3) * 8;

    auto ldslab = [&](int kk) {
        #pragma unroll
        for (int i = 0; i < 2; ++i) {
            int r = lr + i * 64;
            size_t ga = (size_t)(m0 + r) * KD + kk + lc;
            size_t gb = (size_t)(n0 + r) * KD + kk + lc;
            pAh[i] = *reinterpret_cast<const uint4*>(&Ah[ga]);
            pAl[i] = *reinterpret_cast<const uint4*>(&Al[ga]);
            pBh[i] = *reinterpret_cast<const uint4*>(&Bh[gb]);
            pBl[i] = *reinterpret_cast<const uint4*>(&Bl[gb]);
        }
    };
    auto stslab = [&]() {
        #pragma unroll
        for (int i = 0; i < 2; ++i) {
            int r = lr + i * 64;
            *reinterpret_cast<uint4*>(&sAh[r * ST + lc]) = pAh[i];
            *reinterpret_cast<uint4*>(&sAl[r * ST + lc]) = pAl[i];
            *reinterpret_cast<uint4*>(&sBh[r * ST + lc]) = pBh[i];
            *reinterpret_cast<uint4*>(&sBl[r * ST + lc]) = pBl[i];
        }
    };

    ldslab(0);
    for (int kk = 0; kk < KD; kk += 32) {
        stslab();
        __syncthreads();
        if (kk + 32 < KD) ldslab(kk + 32);

        #pragma unroll
        for (int ks = 0; ks < 32; ks += 16) {
            uint32_t rah[4][4], ral[4][4], rbh[4][2], rbl[4][2];
            #pragma unroll
            for (int mi = 0; mi < 4; ++mi) {
                int off = (wm * 64 + mi * 16 + g) * ST + ks + qd * 2;
                rah[mi][0] = *reinterpret_cast<const uint32_t*>(&sAh[off]);
                rah[mi][1] = *reinterpret_cast<const uint32_t*>(&sAh[off + 8 * ST]);
                rah[mi][2] = *reinterpret_cast<const uint32_t*>(&sAh[off + 8]);
                rah[mi][3] = *reinterpret_cast<const uint32_t*>(&sAh[off + 8 * ST + 8]);
                ral[mi][0] = *reinterpret_cast<const uint32_t*>(&sAl[off]);
                ral[mi][1] = *reinterpret_cast<const uint32_t*>(&sAl[off + 8 * ST]);
                ral[mi][2] = *reinterpret_cast<const uint32_t*>(&sAl[off + 8]);
                ral[mi][3] = *reinterpret_cast<const uint32_t*>(&sAl[off + 8 * ST + 8]);
            }
            #pragma unroll
            for (int ni = 0; ni < 4; ++ni) {
                int off = (wn * 32 + ni * 8 + g) * ST + ks + qd * 2;
                rbh[ni][0] = *reinterpret_cast<const uint32_t*>(&sBh[off]);
                rbh[ni][1] = *reinterpret_cast<const uint32_t*>(&sBh[off + 8]);
                rbl[ni][0] = *reinterpret_cast<const uint32_t*>(&sBl[off]);
                rbl[ni][1] = *reinterpret_cast<const uint32_t*>(&sBl[off + 8]);
            }
            #pragma unroll
            for (int mi = 0; mi < 4; ++mi)
                #pragma unroll
                for (int ni = 0; ni < 4; ++ni) {
                    mma_bf16(acc[mi][ni], rah[mi][0], rah[mi][1], rah[mi][2], rah[mi][3],
                             rbh[ni][0], rbh[ni][1]);
                    mma_bf16(acc[mi][ni], rah[mi][0], rah[mi][1], rah[mi][2], rah[mi][3],
                             rbl[ni][0], rbl[ni][1]);
                    mma_bf16(acc[mi][ni], ral[mi][0], ral[mi][1], ral[mi][2], ral[mi][3],
                             rbh[ni][0], rbh[ni][1]);
                }
        }
        __syncthreads();
    }

    #pragma unroll
    for (int mi = 0; mi < 4; ++mi) {
        int row = m0 + wm * 64 + mi * 16 + g;
        #pragma unroll
        for (int ni = 0; ni < 4; ++ni) {
            int col = n0 + wn * 32 + ni * 8 + qd * 2;
            float* c = acc[mi][ni];
            if (BF16OUT) {
                uint32_t h01, l01, h23, l23;
                split2(c[0], c[1], h01, l01);
                split2(c[2], c[3], h23, l23);
                *reinterpret_cast<uint32_t*>(&Ch[(size_t)row * ND + col]) = h01;
                *reinterpret_cast<uint32_t*>(&Cl[(size_t)row * ND + col]) = l01;
                *reinterpret_cast<uint32_t*>(&Ch[(size_t)(row + 8) * ND + col]) = h23;
                *reinterpret_cast<uint32_t*>(&Cl[(size_t)(row + 8) * ND + col]) = l23;
            } else {
                *reinterpret_cast<float2*>(&Cf[(size_t)row * ND + col])       = make_float2(c[0], c[1]);
                *reinterpret_cast<float2*>(&Cf[(size_t)(row + 8) * ND + col]) = make_float2(c[2], c[3]);
            }
        }
    }
}

__global__ __launch_bounds__(256) void proj_gemm() {
    int which = blockIdx.z;
    const bf16* Bh = g_Wh + (size_t)which * Dc * Ec;
    const bf16* Bl = g_Wl + (size_t)which * Dc * Ec;
    bf16* Ch = (which == 0) ? g_Qh : (which == 1) ? g_Kh : g_Vh;
    bf16* Cl = (which == 0) ? g_Ql : (which == 1) ? g_Kl : g_Vl;
    gemm_body<true>(g_Xh, g_Xl, Bh, Bl, nullptr, Ch, Cl);
}
__global__ __launch_bounds__(256) void out_gemm(float* __restrict__ out) {
    gemm_body<false>(g_Ch, g_Cl,
                     g_Wh + (size_t)3 * Dc * Ec, g_Wl + (size_t)3 * Dc * Ec,
                     out, nullptr, nullptr);
}

// ---------------------------------------------------------------------------
// Flash attention, bf16x3 MMA. BQ=64 (4 warps x m16), BKV=64. 128 threads.
// Q frags register-resident; P remapped C->A layout in registers.
// ---------------------------------------------------------------------------
__global__ __launch_bounds__(128) void attn_fwd(const float* __restrict__ mask) {
    constexpr int ST = 72;
    __shared__ bf16 sKh[64 * ST], sKl[64 * ST], sVh[64 * ST], sVl[64 * ST];

    const int tid = threadIdx.x;
    const int wid = tid >> 5, lid = tid & 31;
    const int g = lid >> 2, qd = lid & 3;
    const int qt = blockIdx.x, q0 = qt * 64;
    const int bh = blockIdx.y, b = bh >> 4, h = bh & 15;

    const size_t qkbase = (size_t)b * Sc * Ec + (size_t)h * DKc;
    const size_t vtbase = (size_t)bh * DKc * Sc;
    const int lr = tid >> 3, lc = (tid & 7) * 8;

    // stage Q tile via K smem, lift A-fragments to registers
    #pragma unroll
    for (int i = 0; i < 4; ++i) {
        int r = lr + i * 16;
        size_t gq = qkbase + (size_t)(q0 + r) * Ec + lc;
        *reinterpret_cast<uint4*>(&sKh[r * ST + lc]) = *reinterpret_cast<const uint4*>(&g_Qh[gq]);
        *reinterpret_cast<uint4*>(&sKl[r * ST + lc]) = *reinterpret_cast<const uint4*>(&g_Ql[gq]);
    }
    __syncthreads();

    uint32_t qh[4][4], ql[4][4];
    {
        int rowoff = (wid * 16 + g) * ST;
        #pragma unroll
        for (int kf = 0; kf < 4; ++kf) {
            int off = rowoff + kf * 16 + qd * 2;
            qh[kf][0] = *reinterpret_cast<const uint32_t*>(&sKh[off]);
            qh[kf][1] = *reinterpret_cast<const uint32_t*>(&sKh[off + 8 * ST]);
            qh[kf][2] = *reinterpret_cast<const uint32_t*>(&sKh[off + 8]);
            qh[kf][3] = *reinterpret_cast<const uint32_t*>(&sKh[off + 8 * ST + 8]);
            ql[kf][0] = *reinterpret_cast<const uint32_t*>(&sKl[off]);
            ql[kf][1] = *reinterpret_cast<const uint32_t*>(&sKl[off + 8 * ST]);
            ql[kf][2] = *reinterpret_cast<const uint32_t*>(&sKl[off + 8]);
            ql[kf][3] = *reinterpret_cast<const uint32_t*>(&sKl[off + 8 * ST + 8]);
        }
    }
    __syncthreads();

    float o[8][4];
    #pragma unroll
    for (int nd = 0; nd < 8; ++nd)
        #pragma unroll
        for (int c = 0; c < 4; ++c) o[nd][c] = 0.f;

    float m0r = -3.0e38f, m1r = -3.0e38f, l0r = 0.f, l1r = 0.f;
    const float* mp0 = mask + (size_t)(q0 + wid * 16 + g) * Sc;
    const float* mp1 = mp0 + (size_t)8 * Sc;

    // causal skip: tiles with kv0 > q0+63 are fully masked
    for (int t = 0; t <= qt; ++t) {
        const int kv0 = t * 64;

        #pragma unroll
        for (int i = 0; i < 4; ++i) {
            int r = lr + i * 16;
            size_t gk = qkbase + (size_t)(kv0 + r) * Ec + lc;
            size_t gv = vtbase + (size_t)r * Sc + kv0 + lc;
            *reinterpret_cast<uint4*>(&sKh[r * ST + lc]) = *reinterpret_cast<const uint4*>(&g_Kh[gk]);
            *reinterpret_cast<uint4*>(&sKl[r * ST + lc]) = *reinterpret_cast<const uint4*>(&g_Kl[gk]);
            *reinterpret_cast<uint4*>(&sVh[r * ST + lc]) = *reinterpret_cast<const uint4*>(&g_Vth[gv]);
            *reinterpret_cast<uint4*>(&sVl[r * ST + lc]) = *reinterpret_cast<const uint4*>(&g_Vtl[gv]);
        }
        __syncthreads();

        // S = Q K^T  (bf16x3)
        float s[8][4];
        #pragma unroll
        for (int nf = 0; nf < 8; ++nf)
            #pragma unroll
            for (int c = 0; c < 4; ++c) s[nf][c] = 0.f;

        #pragma unroll
        for (int nf = 0; nf < 8; ++nf) {
            int coloff = (nf * 8 + g) * ST;
            #pragma unroll
            for (int kf = 0; kf < 4; ++kf) {
                int off = coloff + kf * 16 + qd * 2;
                uint32_t kh0 = *reinterpret_cast<const uint32_t*>(&sKh[off]);
                uint32_t kh1 = *reinterpret_cast<const uint32_t*>(&sKh[off + 8]);
                uint32_t kl0 = *reinterpret_cast<const uint32_t*>(&sKl[off]);
                uint32_t kl1 = *reinterpret_cast<const uint32_t*>(&sKl[off + 8]);
                mma_bf16(s[nf], qh[kf][0], qh[kf][1], qh[kf][2], qh[kf][3], kh0, kh1);
                mma_bf16(s[nf], qh[kf][0], qh[kf][1], qh[kf][2], qh[kf][3], kl0, kl1);
                mma_bf16(s[nf], ql[kf][0], ql[kf][1], ql[kf][2], ql[kf][3], kh0, kh1);
            }
        }

        // scale + mask + running row max (rows g and g+8)
        float mx0 = -3.0e38f, mx1 = -3.0e38f;
        #pragma unroll
        for (int nf = 0; nf < 8; ++nf) {
            float2 v0 = *reinterpret_cast<const float2*>(&mp0[kv0 + nf * 8 + qd * 2]);
            float2 v1 = *reinterpret_cast<const float2*>(&mp1[kv0 + nf * 8 + qd * 2]);
            s[nf][0] = s[nf][0] * 0.125f + v0.x;
            s[nf][1] = s[nf][1] * 0.125f + v0.y;
            s[nf][2] = s[nf][2] * 0.125f + v1.x;
            s[nf][3] = s[nf][3] * 0.125f + v1.y;
            mx0 = fmaxf(mx0, fmaxf(s[nf][0], s[nf][1]));
            mx1 = fmaxf(mx1, fmaxf(s[nf][2], s[nf][3]));
        }
        mx0 = fmaxf(mx0, __shfl_xor_sync(0xffffffffu, mx0, 1));
        mx0 = fmaxf(mx0, __shfl_xor_sync(0xffffffffu, mx0, 2));
        mx1 = fmaxf(mx1, __shfl_xor_sync(0xffffffffu, mx1, 1));
        mx1 = fmaxf(mx1, __shfl_xor_sync(0xffffffffu, mx1, 2));

        float mn0 = fmaxf(m0r, mx0), mn1 = fmaxf(m1r, mx1);
        float a0 = __expf(m0r - mn0), a1 = __expf(m1r - mn1);
        m0r = mn0; m1r = mn1;

        // exp + hi/lo split into P A-fragments (register-only C->A remap)
        uint32_t ph[4][4], pl[4][4];
        float rs0 = 0.f, rs1 = 0.f;
        #pragma unroll
        for (int nf = 0; nf < 8; ++nf) {
            float p0 = __expf(s[nf][0] - mn0), p1 = __expf(s[nf][1] - mn0);
            float p2 = __expf(s[nf][2] - mn1), p3 = __expf(s[nf][3] - mn1);
            rs0 += p0 + p1; rs1 += p2 + p3;
            uint32_t h01, l01, h23, l23;
            split2(p0, p1, h01, l01);
            split2(p2, p3, h23, l23);
            int kf = nf >> 1;
            if ((nf & 1) == 0) { ph[kf][0] = h01; ph[kf][1] = h23; pl[kf][0] = l01; pl[kf][1] = l23; }
            else               { ph[kf][2] = h01; ph[kf][3] = h23; pl[kf][2] = l01; pl[kf][3] = l23; }
        }
        rs0 += __shfl_xor_sync(0xffffffffu, rs0, 1);
        rs0 += __shfl_xor_sync(0xffffffffu, rs0, 2);
        rs1 += __shfl_xor_sync(0xffffffffu, rs1, 1);
        rs1 += __shfl_xor_sync(0xffffffffu, rs1, 2);
        l0r = l0r * a0 + rs0;
        l1r = l1r * a1 + rs1;

        #pragma unroll
        for (int nd = 0; nd < 8; ++nd) {
            o[nd][0] *= a0; o[nd][1] *= a0; o[nd][2] *= a1; o[nd][3] *= a1;
        }

        // O += P @ V^T-tile
        #pragma unroll
        for (int nd = 0; nd < 8; ++nd) {
            int coloff = (nd * 8 + g) * ST;
            #pragma unroll
            for (int kf = 0; kf < 4; ++kf) {
                int off = coloff + kf * 16 + qd * 2;
                uint32_t vh0 = *reinterpret_cast<const uint32_t*>(&sVh[off]);
                uint32_t vh1 = *reinterpret_cast<const uint32_t*>(&sVh[off + 8]);
                uint32_t vl0 = *reinterpret_cast<const uint32_t*>(&sVl[off]);
                uint32_t vl1 = *reinterpret_cast<const uint32_t*>(&sVl[off + 8]);
                mma_bf16(o[nd], ph[kf][0], ph[kf][1], ph[kf][2], ph[kf][3], vh0, vh1);
                mma_bf16(o[nd], ph[kf][0], ph[kf][1], ph[kf][2], ph[kf][3], vl0, vl1);
                mma_bf16(o[nd], pl[kf][0], pl[kf][1], pl[kf][2], pl[kf][3], vh0, vh1);
            }
        }
        __syncthreads();
    }

    // normalize + hi/lo split store of ctx
    float inv0 = 1.0f / l0r, inv1 = 1.0f / l1r;
    size_t base = (size_t)(b * Sc + q0 + wid * 16 + g) * Ec + h * DKc;
    #pragma unroll
    for (int nd = 0; nd < 8; ++nd) {
        int col = nd * 8 + qd * 2;
        uint32_t h01, l01, h23, l23;
        split2(o[nd][0] * inv0, o[nd][1] * inv0, h01, l01);
        split2(o[nd][2] * inv1, o[nd][3] * inv1, h23, l23);
        *reinterpret_cast<uint32_t*>(&g_Ch[base + col]) = h01;
        *reinterpret_cast<uint32_t*>(&g_Cl[base + col]) = l01;
        *reinterpret_cast<uint32_t*>(&g_Ch[base + (size_t)8 * Ec + col]) = h23;
        *reinterpret_cast<uint32_t*>(&g_Cl[base + (size_t)8 * Ec + col]) = l23;
    }
}

// ---------------------------------------------------------------------------
extern "C" void kernel_launch(void* const* d_in, const int* in_sizes, int n_in,
                              void* d_out, int out_size)
{
    (void)in_sizes; (void)n_in; (void)out_size;
    const float* hs   = (const float*)d_in[0];
    const float* mask = (const float*)d_in[1];
    const float* Wq   = (const float*)d_in[2];
    const float* Wk   = (const float*)d_in[3];
    const float* Wv   = (const float*)d_in[4];
    const float* Wo   = (const float*)d_in[5];
    float* out        = (float*)d_out;

    split_kernel<<<(Mrows * Dc) / 1024, 256>>>(hs, 0);
    split_kernel<<<(Dc * Ec) / 1024, 256>>>(Wq, 1);
    split_kernel<<<(Dc * Ec) / 1024, 256>>>(Wk, 2);
    split_kernel<<<(Dc * Ec) / 1024, 256>>>(Wv, 3);
    split_kernel<<<(Dc * Ec) / 1024, 256>>>(Wo, 4);

    dim3 gProj(Ec / 128, Mrows / 128, 3);
    proj_gemm<<<gProj, 256>>>();

    dim3 gVt(Sc / 32, DKc / 32, Bc * Hc);
    vtrans_kernel<<<gVt, dim3(32, 8)>>>();

    dim3 gAttn(Sc / 64, Bc * Hc);
    attn_fwd<<<gAttn, 128>>>(mask);

    dim3 gOut(Dc / 128, Mrows / 128);
    out_gemm<<<gOut, 256>>>(out);
}

// round 14
// speedup vs baseline: 1.0031x; 1.0031x over previous
#include <cuda_runtime.h>
#include <cuda_bf16.h>
#include <math.h>
#include <stdint.h>

using bf16 = __nv_bfloat16;

constexpr int Bc  = 4;
constexpr int Sc  = 2048;
constexpr int Dc  = 1024;
constexpr int Hc  = 16;
constexpr int DKc = 64;
constexpr int Mrows = Bc * Sc;     // 8192
constexpr int Ec    = Hc * DKc;    // 1024

// Device-global scratch (allocation-free per harness rules)
__device__ bf16 g_Xh[(size_t)Mrows * Dc];
__device__ bf16 g_Xl[(size_t)Mrows * Dc];
__device__ bf16 g_Wh[(size_t)4 * Dc * Ec];
__device__ bf16 g_Wl[(size_t)4 * Dc * Ec];
__device__ bf16 g_Qh[(size_t)Mrows * Ec];
__device__ bf16 g_Ql[(size_t)Mrows * Ec];
__device__ bf16 g_Kh[(size_t)Mrows * Ec];
__device__ bf16 g_Kl[(size_t)Mrows * Ec];
__device__ bf16 g_Vh[(size_t)Mrows * Ec];
__device__ bf16 g_Vl[(size_t)Mrows * Ec];
__device__ bf16 g_Vth[(size_t)Bc * Hc * DKc * Sc];  // [bh][dk][s]
__device__ bf16 g_Vtl[(size_t)Bc * Hc * DKc * Sc];
__device__ bf16 g_Ch[(size_t)Mrows * Ec];
__device__ bf16 g_Cl[(size_t)Mrows * Ec];

__device__ __forceinline__ uint32_t pack2(bf16 a, bf16 b) {
    __nv_bfloat162 t; t.x = a; t.y = b;
    return *reinterpret_cast<uint32_t*>(&t);
}
__device__ __forceinline__ void split2(float x, float y, uint32_t& hi, uint32_t& lo) {
    bf16 hx = __float2bfloat16(x), hy = __float2bfloat16(y);
    bf16 lx = __float2bfloat16(x - __bfloat162float(hx));
    bf16 ly = __float2bfloat16(y - __bfloat162float(hy));
    hi = pack2(hx, hy); lo = pack2(lx, ly);
}
__device__ __forceinline__ void mma_bf16(float* c,
        uint32_t a0, uint32_t a1, uint32_t a2, uint32_t a3,
        uint32_t b0, uint32_t b1) {
    asm volatile(
        "mma.sync.aligned.m16n8k16.row.col.f32.bf16.bf16.f32 "
        "{%0,%1,%2,%3}, {%4,%5,%6,%7}, {%8,%9}, {%0,%1,%2,%3};\n"
        : "+f"(c[0]), "+f"(c[1]), "+f"(c[2]), "+f"(c[3])
        : "r"(a0), "r"(a1), "r"(a2), "r"(a3), "r"(b0), "r"(b1));
}

// fp32 -> bf16 hi/lo split. which==0 -> X, 1..4 -> W slot.
__global__ __launch_bounds__(256) void split_kernel(const float* __restrict__ x, int which) {
    bf16 *hi, *lo;
    if (which == 0) { hi = g_Xh; lo = g_Xl; }
    else { size_t off = (size_t)(which - 1) * Dc * Ec; hi = g_Wh + off; lo = g_Wl + off; }
    size_t i = ((size_t)blockIdx.x * 256 + threadIdx.x) * 4;
    float4 v = *reinterpret_cast<const float4*>(x + i);
    bf16 h0 = __float2bfloat16(v.x), h1 = __float2bfloat16(v.y);
    bf16 h2 = __float2bfloat16(v.z), h3 = __float2bfloat16(v.w);
    bf16 l0 = __float2bfloat16(v.x - __bfloat162float(h0));
    bf16 l1 = __float2bfloat16(v.y - __bfloat162float(h1));
    bf16 l2 = __float2bfloat16(v.z - __bfloat162float(h2));
    bf16 l3 = __float2bfloat16(v.w - __bfloat162float(h3));
    uint2 H, L;
    H.x = pack2(h0, h1); H.y = pack2(h2, h3);
    L.x = pack2(l0, l1); L.y = pack2(l2, l3);
    *reinterpret_cast<uint2*>(hi + i) = H;
    *reinterpret_cast<uint2*>(lo + i) = L;
}

// V transpose: [b][s][h*64+dk] -> [bh][dk][s]
__global__ __launch_bounds__(256) void vtrans_kernel() {
    __shared__ bf16 th[32][33], tl[32][33];
    const int s0 = blockIdx.x * 32, d0 = blockIdx.y * 32, bh = blockIdx.z;
    const int b = bh >> 4, h = bh & 15;
    #pragma unroll
    for (int j = 0; j < 4; ++j) {
        int s = s0 + threadIdx.y + j * 8;
        size_t src = (size_t)(b * Sc + s) * Ec + h * DKc + d0 + threadIdx.x;
        th[threadIdx.y + j * 8][threadIdx.x] = g_Vh[src];
        tl[threadIdx.y + j * 8][threadIdx.x] = g_Vl[src];
    }
    __syncthreads();
    #pragma unroll
    for (int j = 0; j < 4; ++j) {
        int d = d0 + threadIdx.y + j * 8;
        size_t dst = (size_t)bh * DKc * Sc + (size_t)d * Sc + s0 + threadIdx.x;
        g_Vth[dst] = th[threadIdx.x][threadIdx.y + j * 8];
        g_Vtl[dst] = tl[threadIdx.x][threadIdx.y + j * 8];
    }
}

// ---------------------------------------------------------------------------
// bf16x3 GEMM: C[m][n] = sum_k A[m][k]*B[n][k]; N=K=1024.
// BM=128, BN=128, BK=32, 256 threads, warps 2(m)x4(n). Smem stride 40 bf16.
// ---------------------------------------------------------------------------
template<bool BF16OUT>
__device__ __forceinline__ void gemm_body(
    const bf16* __restrict__ Ah, const bf16* __restrict__ Al,
    const bf16* __restrict__ Bh, const bf16* __restrict__ Bl,
    float* __restrict__ Cf, bf16* __restrict__ Ch, bf16* __restrict__ Cl)
{
    constexpr int KD = 1024, ND = 1024, ST = 40;
    __shared__ bf16 sAh[128 * ST], sAl[128 * ST], sBh[128 * ST], sBl[128 * ST];

    const int tid = threadIdx.x;
    const int wid = tid >> 5, lid = tid & 31;
    const int wm = wid >> 2, wn = wid & 3;
    const int g = lid >> 2, qd = lid & 3;
    const int m0 = blockIdx.y * 128, n0 = blockIdx.x * 128;

    float acc[4][4][4];
    #pragma unroll
    for (int a = 0; a < 4; ++a)
        #pragma unroll
        for (int b = 0; b < 4; ++b)
            #pragma unroll
            for (int c = 0; c < 4; ++c) acc[a][b][c] = 0.f;

    uint4 pAh[2], pAl[2], pBh[2], pBl[2];
    const int lr = tid >> 2, lc = (tid & 3) * 8;

    auto ldslab = [&](int kk) {
        #pragma unroll
        for (int i = 0; i < 2; ++i) {
            int r = lr + i * 64;
            size_t ga = (size_t)(m0 + r) * KD + kk + lc;
            size_t gb = (size_t)(n0 + r) * KD + kk + lc;
            pAh[i] = *reinterpret_cast<const uint4*>(&Ah[ga]);
            pAl[i] = *reinterpret_cast<const uint4*>(&Al[ga]);
            pBh[i] = *reinterpret_cast<const uint4*>(&Bh[gb]);
            pBl[i] = *reinterpret_cast<const uint4*>(&Bl[gb]);
        }
    };
    auto stslab = [&]() {
        #pragma unroll
        for (int i = 0; i < 2; ++i) {
            int r = lr + i * 64;
            *reinterpret_cast<uint4*>(&sAh[r * ST + lc]) = pAh[i];
            *reinterpret_cast<uint4*>(&sAl[r * ST + lc]) = pAl[i];
            *reinterpret_cast<uint4*>(&sBh[r * ST + lc]) = pBh[i];
            *reinterpret_cast<uint4*>(&sBl[r * ST + lc]) = pBl[i];
        }
    };

    ldslab(0);
    for (int kk = 0; kk < KD; kk += 32) {
        stslab();
        __syncthreads();
        if (kk + 32 < KD) ldslab(kk + 32);

        #pragma unroll
        for (int ks = 0; ks < 32; ks += 16) {
            uint32_t rah[4][4], ral[4][4], rbh[4][2], rbl[4][2];
            #pragma unroll
            for (int mi = 0; mi < 4; ++mi) {
                int off = (wm * 64 + mi * 16 + g) * ST + ks + qd * 2;
                rah[mi][0] = *reinterpret_cast<const uint32_t*>(&sAh[off]);
                rah[mi][1] = *reinterpret_cast<const uint32_t*>(&sAh[off + 8 * ST]);
                rah[mi][2] = *reinterpret_cast<const uint32_t*>(&sAh[off + 8]);
                rah[mi][3] = *reinterpret_cast<const uint32_t*>(&sAh[off + 8 * ST + 8]);
                ral[mi][0] = *reinterpret_cast<const uint32_t*>(&sAl[off]);
                ral[mi][1] = *reinterpret_cast<const uint32_t*>(&sAl[off + 8 * ST]);
                ral[mi][2] = *reinterpret_cast<const uint32_t*>(&sAl[off + 8]);
                ral[mi][3] = *reinterpret_cast<const uint32_t*>(&sAl[off + 8 * ST + 8]);
            }
            #pragma unroll
            for (int ni = 0; ni < 4; ++ni) {
                int off = (wn * 32 + ni * 8 + g) * ST + ks + qd * 2;
                rbh[ni][0] = *reinterpret_cast<const uint32_t*>(&sBh[off]);
                rbh[ni][1] = *reinterpret_cast<const uint32_t*>(&sBh[off + 8]);
                rbl[ni][0] = *reinterpret_cast<const uint32_t*>(&sBl[off]);
                rbl[ni][1] = *reinterpret_cast<const uint32_t*>(&sBl[off + 8]);
            }
            #pragma unroll
            for (int mi = 0; mi < 4; ++mi)
                #pragma unroll
                for (int ni = 0; ni < 4; ++ni) {
                    mma_bf16(acc[mi][ni], rah[mi][0], rah[mi][1], rah[mi][2], rah[mi][3],
                             rbh[ni][0], rbh[ni][1]);
                    mma_bf16(acc[mi][ni], rah[mi][0], rah[mi][1], rah[mi][2], rah[mi][3],
                             rbl[ni][0], rbl[ni][1]);
                    mma_bf16(acc[mi][ni], ral[mi][0], ral[mi][1], ral[mi][2], ral[mi][3],
                             rbh[ni][0], rbh[ni][1]);
                }
        }
        __syncthreads();
    }

    #pragma unroll
    for (int mi = 0; mi < 4; ++mi) {
        int row = m0 + wm * 64 + mi * 16 + g;
        #pragma unroll
        for (int ni = 0; ni < 4; ++ni) {
            int col = n0 + wn * 32 + ni * 8 + qd * 2;
            float* c = acc[mi][ni];
            if (BF16OUT) {
                uint32_t h01, l01, h23, l23;
                split2(c[0], c[1], h01, l01);
                split2(c[2], c[3], h23, l23);
                *reinterpret_cast<uint32_t*>(&Ch[(size_t)row * ND + col]) = h01;
                *reinterpret_cast<uint32_t*>(&Cl[(size_t)row * ND + col]) = l01;
                *reinterpret_cast<uint32_t*>(&Ch[(size_t)(row + 8) * ND + col]) = h23;
                *reinterpret_cast<uint32_t*>(&Cl[(size_t)(row + 8) * ND + col]) = l23;
            } else {
                *reinterpret_cast<float2*>(&Cf[(size_t)row * ND + col])       = make_float2(c[0], c[1]);
                *reinterpret_cast<float2*>(&Cf[(size_t)(row + 8) * ND + col]) = make_float2(c[2], c[3]);
            }
        }
    }
}

__global__ __launch_bounds__(256) void proj_gemm() {
    int which = blockIdx.z;
    const bf16* Bh = g_Wh + (size_t)which * Dc * Ec;
    const bf16* Bl = g_Wl + (size_t)which * Dc * Ec;
    bf16* Ch = (which == 0) ? g_Qh : (which == 1) ? g_Kh : g_Vh;
    bf16* Cl = (which == 0) ? g_Ql : (which == 1) ? g_Kl : g_Vl;
    gemm_body<true>(g_Xh, g_Xl, Bh, Bl, nullptr, Ch, Cl);
}
__global__ __launch_bounds__(256) void out_gemm(float* __restrict__ out) {
    gemm_body<false>(g_Ch, g_Cl,
                     g_Wh + (size_t)3 * Dc * Ec, g_Wl + (size_t)3 * Dc * Ec,
                     out, nullptr, nullptr);
}

// ---------------------------------------------------------------------------
// Flash attention, bf16x3 MMA. BQ=64 (4 warps x m16), BKV=64. 128 threads.
// Q frags register-resident; P remapped C->A layout in registers.
// ---------------------------------------------------------------------------
__global__ __launch_bounds__(128) void attn_fwd(const float* __restrict__ mask) {
    constexpr int ST = 72;
    __shared__ bf16 sKh[64 * ST], sKl[64 * ST], sVh[64 * ST], sVl[64 * ST];

    const int tid = threadIdx.x;
    const int wid = tid >> 5, lid = tid & 31;
    const int g = lid >> 2, qd = lid & 3;
    const int qt = blockIdx.x, q0 = qt * 64;
    const int bh = blockIdx.y, b = bh >> 4, h = bh & 15;

    const size_t qkbase = (size_t)b * Sc * Ec + (size_t)h * DKc;
    const size_t vtbase = (size_t)bh * DKc * Sc;
    const int lr = tid >> 3, lc = (tid & 7) * 8;

    // stage Q tile via K smem, lift A-fragments to registers
    #pragma unroll
    for (int i = 0; i < 4; ++i) {
        int r = lr + i * 16;
        size_t gq = qkbase + (size_t)(q0 + r) * Ec + lc;
        *reinterpret_cast<uint4*>(&sKh[r * ST + lc]) = *reinterpret_cast<const uint4*>(&g_Qh[gq]);
        *reinterpret_cast<uint4*>(&sKl[r * ST + lc]) = *reinterpret_cast<const uint4*>(&g_Ql[gq]);
    }
    __syncthreads();

    uint32_t qh[4][4], ql[4][4];
    {
        int rowoff = (wid * 16 + g) * ST;
        #pragma unroll
        for (int kf = 0; kf < 4; ++kf) {
            int off = rowoff + kf * 16 + qd * 2;
            qh[kf][0] = *reinterpret_cast<const uint32_t*>(&sKh[off]);
            qh[kf][1] = *reinterpret_cast<const uint32_t*>(&sKh[off + 8 * ST]);
            qh[kf][2] = *reinterpret_cast<const uint32_t*>(&sKh[off + 8]);
            qh[kf][3] = *reinterpret_cast<const uint32_t*>(&sKh[off + 8 * ST + 8]);
            ql[kf][0] = *reinterpret_cast<const uint32_t*>(&sKl[off]);
            ql[kf][1] = *reinterpret_cast<const uint32_t*>(&sKl[off + 8 * ST]);
            ql[kf][2] = *reinterpret_cast<const uint32_t*>(&sKl[off + 8]);
            ql[kf][3] = *reinterpret_cast<const uint32_t*>(&sKl[off + 8 * ST + 8]);
        }
    }
    __syncthreads();

    float o[8][4];
    #pragma unroll
    for (int nd = 0; nd < 8; ++nd)
        #pragma unroll
        for (int c = 0; c < 4; ++c) o[nd][c] = 0.f;

    float m0r = -3.0e38f, m1r = -3.0e38f, l0r = 0.f, l1r = 0.f;
    const float* mp0 = mask + (size_t)(q0 + wid * 16 + g) * Sc;
    const float* mp1 = mp0 + (size_t)8 * Sc;

    // causal skip: tiles with kv0 > q0+63 are fully masked
    for (int t = 0; t <= qt; ++t) {
        const int kv0 = t * 64;

        #pragma unroll
        for (int i = 0; i < 4; ++i) {
            int r = lr + i * 16;
            size_t gk = qkbase + (size_t)(kv0 + r) * Ec + lc;
            size_t gv = vtbase + (size_t)r * Sc + kv0 + lc;
            *reinterpret_cast<uint4*>(&sKh[r * ST + lc]) = *reinterpret_cast<const uint4*>(&g_Kh[gk]);
            *reinterpret_cast<uint4*>(&sKl[r * ST + lc]) = *reinterpret_cast<const uint4*>(&g_Kl[gk]);
            *reinterpret_cast<uint4*>(&sVh[r * ST + lc]) = *reinterpret_cast<const uint4*>(&g_Vth[gv]);
            *reinterpret_cast<uint4*>(&sVl[r * ST + lc]) = *reinterpret_cast<const uint4*>(&g_Vtl[gv]);
        }
        __syncthreads();

        // S = Q K^T  (bf16x3)
        float s[8][4];
        #pragma unroll
        for (int nf = 0; nf < 8; ++nf)
            #pragma unroll
            for (int c = 0; c < 4; ++c) s[nf][c] = 0.f;

        #pragma unroll
        for (int nf = 0; nf < 8; ++nf) {
            int coloff = (nf * 8 + g) * ST;
            #pragma unroll
            for (int kf = 0; kf < 4; ++kf) {
                int off = coloff + kf * 16 + qd * 2;
                uint32_t kh0 = *reinterpret_cast<const uint32_t*>(&sKh[off]);
                uint32_t kh1 = *reinterpret_cast<const uint32_t*>(&sKh[off + 8]);
                uint32_t kl0 = *reinterpret_cast<const uint32_t*>(&sKl[off]);
                uint32_t kl1 = *reinterpret_cast<const uint32_t*>(&sKl[off + 8]);
                mma_bf16(s[nf], qh[kf][0], qh[kf][1], qh[kf][2], qh[kf][3], kh0, kh1);
                mma_bf16(s[nf], qh[kf][0], qh[kf][1], qh[kf][2], qh[kf][3], kl0, kl1);
                mma_bf16(s[nf], ql[kf][0], ql[kf][1], ql[kf][2], ql[kf][3], kh0, kh1);
            }
        }

        // scale + mask + running row max (rows g and g+8)
        float mx0 = -3.0e38f, mx1 = -3.0e38f;
        #pragma unroll
        for (int nf = 0; nf < 8; ++nf) {
            float2 v0 = *reinterpret_cast<const float2*>(&mp0[kv0 + nf * 8 + qd * 2]);
            float2 v1 = *reinterpret_cast<const float2*>(&mp1[kv0 + nf * 8 + qd * 2]);
            s[nf][0] = s[nf][0] * 0.125f + v0.x;
            s[nf][1] = s[nf][1] * 0.125f + v0.y;
            s[nf][2] = s[nf][2] * 0.125f + v1.x;
            s[nf][3] = s[nf][3] * 0.125f + v1.y;
            mx0 = fmaxf(mx0, fmaxf(s[nf][0], s[nf][1]));
            mx1 = fmaxf(mx1, fmaxf(s[nf][2], s[nf][3]));
        }
        mx0 = fmaxf(mx0, __shfl_xor_sync(0xffffffffu, mx0, 1));
        mx0 = fmaxf(mx0, __shfl_xor_sync(0xffffffffu, mx0, 2));
        mx1 = fmaxf(mx1, __shfl_xor_sync(0xffffffffu, mx1, 1));
        mx1 = fmaxf(mx1, __shfl_xor_sync(0xffffffffu, mx1, 2));

        float mn0 = fmaxf(m0r, mx0), mn1 = fmaxf(m1r, mx1);
        float a0 = __expf(m0r - mn0), a1 = __expf(m1r - mn1);
        m0r = mn0; m1r = mn1;

        // exp + hi/lo split into P A-fragments (register-only C->A remap)
        uint32_t ph[4][4], pl[4][4];
        float rs0 = 0.f, rs1 = 0.f;
        #pragma unroll
        for (int nf = 0; nf < 8; ++nf) {
            float p0 = __expf(s[nf][0] - mn0), p1 = __expf(s[nf][1] - mn0);
            float p2 = __expf(s[nf][2] - mn1), p3 = __expf(s[nf][3] - mn1);
            rs0 += p0 + p1; rs1 += p2 + p3;
            uint32_t h01, l01, h23, l23;
            split2(p0, p1, h01, l01);
            split2(p2, p3, h23, l23);
            int kf = nf >> 1;
            if ((nf & 1) == 0) { ph[kf][0] = h01; ph[kf][1] = h23; pl[kf][0] = l01; pl[kf][1] = l23; }
            else               { ph[kf][2] = h01; ph[kf][3] = h23; pl[kf][2] = l01; pl[kf][3] = l23; }
        }
        rs0 += __shfl_xor_sync(0xffffffffu, rs0, 1);
        rs0 += __shfl_xor_sync(0xffffffffu, rs0, 2);
        rs1 += __shfl_xor_sync(0xffffffffu, rs1, 1);
        rs1 += __shfl_xor_sync(0xffffffffu, rs1, 2);
        l0r = l0r * a0 + rs0;
        l1r = l1r * a1 + rs1;

        #pragma unroll
        for (int nd = 0; nd < 8; ++nd) {
            o[nd][0] *= a0; o[nd][1] *= a0; o[nd][2] *= a1; o[nd][3] *= a1;
        }

        // O += P @ V^T-tile
        #pragma unroll
        for (int nd = 0; nd < 8; ++nd) {
            int coloff = (nd * 8 + g) * ST;
            #pragma unroll
            for (int kf = 0; kf < 4; ++kf) {
                int off = coloff + kf * 16 + qd * 2;
                uint32_t vh0 = *reinterpret_cast<const uint32_t*>(&sVh[off]);
                uint32_t vh1 = *reinterpret_cast<const uint32_t*>(&sVh[off + 8]);
                uint32_t vl0 = *reinterpret_cast<const uint32_t*>(&sVl[off]);
                uint32_t vl1 = *reinterpret_cast<const uint32_t*>(&sVl[off + 8]);
                mma_bf16(o[nd], ph[kf][0], ph[kf][1], ph[kf][2], ph[kf][3], vh0, vh1);
                mma_bf16(o[nd], ph[kf][0], ph[kf][1], ph[kf][2], ph[kf][3], vl0, vl1);
                mma_bf16(o[nd], pl[kf][0], pl[kf][1], pl[kf][2], pl[kf][3], vh0, vh1);
            }
        }
        __syncthreads();
    }

    // normalize + hi/lo split store of ctx
    float inv0 = 1.0f / l0r, inv1 = 1.0f / l1r;
    size_t base = (size_t)(b * Sc + q0 + wid * 16 + g) * Ec + h * DKc;
    #pragma unroll
    for (int nd = 0; nd < 8; ++nd) {
        int col = nd * 8 + qd * 2;
        uint32_t h01, l01, h23, l23;
        split2(o[nd][0] * inv0, o[nd][1] * inv0, h01, l01);
        split2(o[nd][2] * inv1, o[nd][3] * inv1, h23, l23);
        *reinterpret_cast<uint32_t*>(&g_Ch[base + col]) = h01;
        *reinterpret_cast<uint32_t*>(&g_Cl[base + col]) = l01;
        *reinterpret_cast<uint32_t*>(&g_Ch[base + (size_t)8 * Ec + col]) = h23;
        *reinterpret_cast<uint32_t*>(&g_Cl[base + (size_t)8 * Ec + col]) = l23;
    }
}

// ---------------------------------------------------------------------------
extern "C" void kernel_launch(void* const* d_in, const int* in_sizes, int n_in,
                              void* d_out, int out_size)
{
    (void)in_sizes; (void)n_in; (void)out_size;
    const float* hs   = (const float*)d_in[0];
    const float* mask = (const float*)d_in[1];
    const float* Wq   = (const float*)d_in[2];
    const float* Wk   = (const float*)d_in[3];
    const float* Wv   = (const float*)d_in[4];
    const float* Wo   = (const float*)d_in[5];
    float* out        = (float*)d_out;

    split_kernel<<<(Mrows * Dc) / 1024, 256>>>(hs, 0);
    split_kernel<<<(Dc * Ec) / 1024, 256>>>(Wq, 1);
    split_kernel<<<(Dc * Ec) / 1024, 256>>>(Wk, 2);
    split_kernel<<<(Dc * Ec) / 1024, 256>>>(Wv, 3);
    split_kernel<<<(Dc * Ec) / 1024, 256>>>(Wo, 4);

    dim3 gProj(Ec / 128, Mrows / 128, 3);
    proj_gemm<<<gProj, 256>>>();

    dim3 gVt(Sc / 32, DKc / 32, Bc * Hc);
    vtrans_kernel<<<gVt, dim3(32, 8)>>>();

    dim3 gAttn(Sc / 64, Bc * Hc);
    attn_fwd<<<gAttn, 128>>>(mask);

    dim3 gOut(Dc / 128, Mrows / 128);
    out_gemm<<<gOut, 256>>>(out);
}